// round 1
// baseline (speedup 1.0000x reference)
#include <cuda_runtime.h>
#include <cstddef>

#define Bb 64
#define Tt 2048
#define Hh 512
#define Pp 256
#define CHUNKS 8     // CTAs per batch row
#define NWARPS 8     // warps per CTA
#define LOG2E 1.4426950408889634f

// ---- device scratch (no allocations allowed) ----
__device__ float g_kq[Bb * Hh];          // Wk @ q per batch  (128 KB)
__device__ float g_bkq[Bb];              // bk · q per batch
__device__ float g_raw[Bb * Tt];         // raw attention logits (512 KB)
__device__ float g_pm[Bb * 64];          // per-warp-chunk running max
__device__ float g_pz[Bb * 64];          // per-warp-chunk exp-sum
__device__ float g_pacc[(size_t)Bb * 64 * Hh];  // per-warp-chunk weighted enc sums (8 MB)

__device__ __forceinline__ float fexp2(float x) {
    float y;
    asm("ex2.approx.f32 %0, %1;" : "=f"(y) : "f"(x));
    return y;
}

// ---------------------------------------------------------------------------
// Kernel 1: per-batch query projection, then fold Wk/bk into the query:
//   q = dec[b] @ Wq + bq                (P)
//   kq[b] = Wk @ q                      (H)     raw[b,t] = enc[b,t]·kq + bkq
//   bkq[b] = bk · q
// ---------------------------------------------------------------------------
__global__ __launch_bounds__(256) void k_query(
    const float* __restrict__ dec,
    const float* __restrict__ Wq, const float* __restrict__ bq,
    const float* __restrict__ Wk, const float* __restrict__ bk)
{
    __shared__ float sdec[Hh];
    __shared__ float sq[Pp];
    __shared__ float sred[8];
    const int b = blockIdx.x, tid = threadIdx.x;

    sdec[tid]       = dec[b * Hh + tid];
    sdec[tid + 256] = dec[b * Hh + 256 + tid];
    __syncthreads();

    // q[tid] = dec[b]·Wq[:,tid] + bq[tid]   (coalesced Wq reads)
    float acc = bq[tid];
#pragma unroll 8
    for (int d = 0; d < Hh; d++)
        acc = fmaf(sdec[d], Wq[d * Pp + tid], acc);
    sq[tid] = acc;

    // bkq = bk · q  (block reduction)
    float r = bk[tid] * acc;
#pragma unroll
    for (int o = 16; o; o >>= 1) r += __shfl_xor_sync(0xffffffffu, r, o);
    if ((tid & 31) == 0) sred[tid >> 5] = r;
    __syncthreads();
    if (tid == 0) {
        float s = 0.f;
#pragma unroll
        for (int i = 0; i < 8; i++) s += sred[i];
        g_bkq[b] = s;
    }

    // kq[e] = Wk[e,:] · q   (each thread streams one Wk row as float4)
    for (int e = tid; e < Hh; e += 256) {
        const float4* w4 = (const float4*)(Wk + (size_t)e * Pp);
        float a = 0.f;
#pragma unroll 8
        for (int p = 0; p < Pp / 4; p++) {
            float4 w = w4[p];
            a = fmaf(w.x, sq[4 * p + 0], a);
            a = fmaf(w.y, sq[4 * p + 1], a);
            a = fmaf(w.z, sq[4 * p + 2], a);
            a = fmaf(w.w, sq[4 * p + 3], a);
        }
        g_kq[b * Hh + e] = a;
    }
}

// ---------------------------------------------------------------------------
// Kernel 2: the single HBM streaming pass over encoder_outputs (256 MB).
// Warp-per-timestep: 32 lanes x 4 float4 = 512 floats. Online softmax with
// register-resident accumulator (16 floats/lane). No smem, no bar.sync.
// Grid: B*CHUNKS = 512 CTAs x 256 threads (8 warps). Each warp: 32 timesteps.
// ---------------------------------------------------------------------------
__global__ __launch_bounds__(256) void k_stream(const float* __restrict__ enc)
{
    const int lane = threadIdx.x & 31;
    const int warp = threadIdx.x >> 5;
    const int b     = blockIdx.x >> 3;       // /CHUNKS
    const int chunk = blockIdx.x & 7;
    const int pid   = (b << 6) | (chunk << 3) | warp;   // 64 warp-chunks per b
    const int t0    = chunk * (Tt / CHUNKS) + warp * 32;

    const float4* kq4 = (const float4*)(g_kq + (size_t)b * Hh);
    const float4 k0 = kq4[lane], k1 = kq4[32 + lane],
                 k2 = kq4[64 + lane], k3 = kq4[96 + lane];
    const float bkq = g_bkq[b];

    float4 a0 = {0.f, 0.f, 0.f, 0.f}, a1 = a0, a2 = a0, a3 = a0;
    float m = -3.0e38f, Z = 0.f, myS = 0.f;

    const float4* base = (const float4*)(enc + ((size_t)b * Tt + t0) * Hh);

#pragma unroll 4
    for (int i = 0; i < 32; i++) {
        const float4* row = base + (size_t)i * (Hh / 4);
        float4 v0 = row[lane], v1 = row[32 + lane],
               v2 = row[64 + lane], v3 = row[96 + lane];

        float d;
        d = v0.x * k0.x;
        d = fmaf(v0.y, k0.y, d); d = fmaf(v0.z, k0.z, d); d = fmaf(v0.w, k0.w, d);
        d = fmaf(v1.x, k1.x, d); d = fmaf(v1.y, k1.y, d);
        d = fmaf(v1.z, k1.z, d); d = fmaf(v1.w, k1.w, d);
        d = fmaf(v2.x, k2.x, d); d = fmaf(v2.y, k2.y, d);
        d = fmaf(v2.z, k2.z, d); d = fmaf(v2.w, k2.w, d);
        d = fmaf(v3.x, k3.x, d); d = fmaf(v3.y, k3.y, d);
        d = fmaf(v3.z, k3.z, d); d = fmaf(v3.w, k3.w, d);

        d += __shfl_xor_sync(0xffffffffu, d, 16);
        d += __shfl_xor_sync(0xffffffffu, d, 8);
        d += __shfl_xor_sync(0xffffffffu, d, 4);
        d += __shfl_xor_sync(0xffffffffu, d, 2);
        d += __shfl_xor_sync(0xffffffffu, d, 1);

        const float s = d + bkq;
        if (i == lane) myS = s;       // stash for coalesced logit store

        const float mn   = fmaxf(m, s);
        const float corr = fexp2((m - mn) * LOG2E);   // exp(m - mn); 0 on first iter
        const float w    = fexp2((s - mn) * LOG2E);   // exp(s - mn)
        Z = fmaf(Z, corr, w);
        a0.x = fmaf(a0.x, corr, w * v0.x); a0.y = fmaf(a0.y, corr, w * v0.y);
        a0.z = fmaf(a0.z, corr, w * v0.z); a0.w = fmaf(a0.w, corr, w * v0.w);
        a1.x = fmaf(a1.x, corr, w * v1.x); a1.y = fmaf(a1.y, corr, w * v1.y);
        a1.z = fmaf(a1.z, corr, w * v1.z); a1.w = fmaf(a1.w, corr, w * v1.w);
        a2.x = fmaf(a2.x, corr, w * v2.x); a2.y = fmaf(a2.y, corr, w * v2.y);
        a2.z = fmaf(a2.z, corr, w * v2.z); a2.w = fmaf(a2.w, corr, w * v2.w);
        a3.x = fmaf(a3.x, corr, w * v3.x); a3.y = fmaf(a3.y, corr, w * v3.y);
        a3.z = fmaf(a3.z, corr, w * v3.z); a3.w = fmaf(a3.w, corr, w * v3.w);
        m = mn;
    }

    g_raw[b * Tt + t0 + lane] = myS;
    if (lane == 0) { g_pm[pid] = m; g_pz[pid] = Z; }
    float4* pa = (float4*)(g_pacc + (size_t)pid * Hh);
    pa[lane] = a0; pa[32 + lane] = a1; pa[64 + lane] = a2; pa[96 + lane] = a3;
}

// ---------------------------------------------------------------------------
// Kernel 3: combine 64 partials per batch row, project through Wv, emit both
// outputs: context [B,P] then attn [B,T] (tuple flatten order).
// ---------------------------------------------------------------------------
__global__ __launch_bounds__(256) void k_final(
    const float* __restrict__ Wv, const float* __restrict__ bv,
    float* __restrict__ out)
{
    __shared__ float sm[64], sz[64], ssc[64], sctx[Hh];
    const int b = blockIdx.x, tid = threadIdx.x;

    if (tid < 64) { sm[tid] = g_pm[b * 64 + tid]; sz[tid] = g_pz[b * 64 + tid]; }
    __syncthreads();

    float mstar = -3.0e38f;
#pragma unroll
    for (int i = 0; i < 64; i++) mstar = fmaxf(mstar, sm[i]);
    float Z = 0.f;
#pragma unroll
    for (int i = 0; i < 64; i++) Z += sz[i] * fexp2((sm[i] - mstar) * LOG2E);
    if (tid < 64) ssc[tid] = fexp2((sm[tid] - mstar) * LOG2E);
    __syncthreads();

    const float invZ = 1.f / Z;

    // ctx_enc[e] = (1/Z) * sum_i scale_i * acc_i[e]
    for (int e = tid; e < Hh; e += 256) {
        float a = 0.f;
#pragma unroll 8
        for (int i = 0; i < 64; i++)
            a = fmaf(g_pacc[(size_t)(b * 64 + i) * Hh + e], ssc[i], a);
        sctx[e] = a * invZ;
    }
    __syncthreads();

    // context[b,p] = ctx_enc · Wv[:,p] + bv[p]   (coalesced Wv reads)
    float c = bv[tid];
#pragma unroll 8
    for (int e = 0; e < Hh; e++)
        c = fmaf(sctx[e], Wv[e * Pp + tid], c);
    out[b * Pp + tid] = c;

    // attn[b,t] = exp(raw - mstar) / Z
    float* oat = out + Bb * Pp + b * Tt;
    const float* rr = g_raw + b * Tt;
    for (int t = tid; t < Tt; t += 256)
        oat[t] = fexp2((rr[t] - mstar) * LOG2E) * invZ;
}

// ---------------------------------------------------------------------------
extern "C" void kernel_launch(void* const* d_in, const int* in_sizes, int n_in,
                              void* d_out, int out_size)
{
    const float* dec = (const float*)d_in[0];   // [B, DEC_H]
    const float* enc = (const float*)d_in[1];   // [B, T, ENC_H]
    // d_in[2] = encoder_lens (unused by the reference)
    const float* Wk  = (const float*)d_in[3];   // [ENC_H, P]
    const float* bk  = (const float*)d_in[4];   // [P]
    const float* Wv  = (const float*)d_in[5];   // [ENC_H, P]
    const float* bv  = (const float*)d_in[6];   // [P]
    const float* Wq  = (const float*)d_in[7];   // [DEC_H, P]
    const float* bq  = (const float*)d_in[8];   // [P]
    float* out = (float*)d_out;                 // [B*P] context, then [B*T] attn

    k_query<<<Bb, 256>>>(dec, Wq, bq, Wk, bk);
    k_stream<<<Bb * CHUNKS, 256>>>(enc);
    k_final<<<Bb, 256>>>(Wv, bv, out);
}

// round 2
// speedup vs baseline: 1.4206x; 1.4206x over previous
#include <cuda_runtime.h>
#include <cstddef>

#define Bb 64
#define Tt 2048
#define Hh 512
#define Pp 256
#define CHUNKS 8     // stream CTAs per batch row
#define LOG2E 1.4426950408889634f

// ---- device scratch (no allocations allowed) ----
__device__ float g_q[Bb * Pp];           // q = dec@Wq + bq          (64 KB)
__device__ float g_kq[Bb * Hh];          // Wk @ q per batch         (128 KB)
__device__ float g_bkq[Bb];              // bk . q per batch
__device__ float g_raw[Bb * Tt];         // raw attention logits     (512 KB)
__device__ float g_pm[Bb * 64];          // per-warp-chunk running max
__device__ float g_pz[Bb * 64];          // per-warp-chunk exp-sum
__device__ float g_pacc[(size_t)Bb * 64 * Hh];  // partial weighted enc sums (8 MB)

__device__ __forceinline__ float fexp2(float x) {
    float y;
    asm("ex2.approx.f32 %0, %1;" : "=f"(y) : "f"(x));
    return y;
}

// ---------------------------------------------------------------------------
// Kernel 1: q[b] = dec[b] @ Wq + bq ; bkq[b] = bk . q[b]
// Batched loads (16 in flight) + 4 independent accumulators -> high MLP.
// ---------------------------------------------------------------------------
__global__ __launch_bounds__(256) void k_query(
    const float* __restrict__ dec,
    const float* __restrict__ Wq, const float* __restrict__ bq,
    const float* __restrict__ bk)
{
    __shared__ float sdec[Hh];
    __shared__ float sred[8];
    const int b = blockIdx.x, tid = threadIdx.x;

    sdec[tid]       = dec[b * Hh + tid];
    sdec[tid + 256] = dec[b * Hh + 256 + tid];
    __syncthreads();

    float a0 = 0.f, a1 = 0.f, a2 = 0.f, a3 = 0.f;
#pragma unroll 4
    for (int d0 = 0; d0 < Hh; d0 += 16) {
        float w[16];
#pragma unroll
        for (int j = 0; j < 16; j++) w[j] = Wq[(d0 + j) * Pp + tid];
#pragma unroll
        for (int j = 0; j < 16; j += 4) {
            a0 = fmaf(sdec[d0 + j + 0], w[j + 0], a0);
            a1 = fmaf(sdec[d0 + j + 1], w[j + 1], a1);
            a2 = fmaf(sdec[d0 + j + 2], w[j + 2], a2);
            a3 = fmaf(sdec[d0 + j + 3], w[j + 3], a3);
        }
    }
    const float q = ((a0 + a1) + (a2 + a3)) + bq[tid];
    g_q[b * Pp + tid] = q;

    // bkq = bk . q  (block reduction)
    float r = bk[tid] * q;
#pragma unroll
    for (int o = 16; o; o >>= 1) r += __shfl_xor_sync(0xffffffffu, r, o);
    if ((tid & 31) == 0) sred[tid >> 5] = r;
    __syncthreads();
    if (tid == 0) {
        float s = 0.f;
#pragma unroll
        for (int i = 0; i < 8; i++) s += sred[i];
        g_bkq[b] = s;
    }
}

// ---------------------------------------------------------------------------
// Kernel 2: kq[b,e] = Wk[e,:] . q[b].  Grid (4, B) x 128 threads: one thread
// per output e; float4 row stream, batched (8 LDG.128 in flight), 4 accs.
// ---------------------------------------------------------------------------
__global__ __launch_bounds__(128) void k_kq(const float* __restrict__ Wk)
{
    __shared__ float sq[Pp];
    const int b = blockIdx.y, tid = threadIdx.x;
    const int e = blockIdx.x * 128 + tid;

    sq[tid]       = g_q[b * Pp + tid];
    sq[tid + 128] = g_q[b * Pp + 128 + tid];
    __syncthreads();

    const float4* w4 = (const float4*)(Wk + (size_t)e * Pp);
    float a0 = 0.f, a1 = 0.f, a2 = 0.f, a3 = 0.f;
#pragma unroll
    for (int p = 0; p < Pp / 4; p += 8) {
        float4 w[8];
#pragma unroll
        for (int j = 0; j < 8; j++) w[j] = w4[p + j];
#pragma unroll
        for (int j = 0; j < 8; j++) {
            a0 = fmaf(w[j].x, sq[4 * (p + j) + 0], a0);
            a1 = fmaf(w[j].y, sq[4 * (p + j) + 1], a1);
            a2 = fmaf(w[j].z, sq[4 * (p + j) + 2], a2);
            a3 = fmaf(w[j].w, sq[4 * (p + j) + 3], a3);
        }
    }
    g_kq[b * Hh + e] = (a0 + a1) + (a2 + a3);
}

// ---------------------------------------------------------------------------
// Kernel 3: single HBM streaming pass over encoder_outputs (256 MB).
// Warp-per-timestep, online softmax, register accumulator. (Near roofline —
// unchanged from R1.)
// ---------------------------------------------------------------------------
__global__ __launch_bounds__(256) void k_stream(const float* __restrict__ enc)
{
    const int lane = threadIdx.x & 31;
    const int warp = threadIdx.x >> 5;
    const int b     = blockIdx.x >> 3;
    const int chunk = blockIdx.x & 7;
    const int pid   = (b << 6) | (chunk << 3) | warp;
    const int t0    = chunk * (Tt / CHUNKS) + warp * 32;

    const float4* kq4 = (const float4*)(g_kq + (size_t)b * Hh);
    const float4 k0 = kq4[lane], k1 = kq4[32 + lane],
                 k2 = kq4[64 + lane], k3 = kq4[96 + lane];
    const float bkq = g_bkq[b];

    float4 a0 = {0.f, 0.f, 0.f, 0.f}, a1 = a0, a2 = a0, a3 = a0;
    float m = -3.0e38f, Z = 0.f, myS = 0.f;

    const float4* base = (const float4*)(enc + ((size_t)b * Tt + t0) * Hh);

#pragma unroll 4
    for (int i = 0; i < 32; i++) {
        const float4* row = base + (size_t)i * (Hh / 4);
        float4 v0 = row[lane], v1 = row[32 + lane],
               v2 = row[64 + lane], v3 = row[96 + lane];

        float d;
        d = v0.x * k0.x;
        d = fmaf(v0.y, k0.y, d); d = fmaf(v0.z, k0.z, d); d = fmaf(v0.w, k0.w, d);
        d = fmaf(v1.x, k1.x, d); d = fmaf(v1.y, k1.y, d);
        d = fmaf(v1.z, k1.z, d); d = fmaf(v1.w, k1.w, d);
        d = fmaf(v2.x, k2.x, d); d = fmaf(v2.y, k2.y, d);
        d = fmaf(v2.z, k2.z, d); d = fmaf(v2.w, k2.w, d);
        d = fmaf(v3.x, k3.x, d); d = fmaf(v3.y, k3.y, d);
        d = fmaf(v3.z, k3.z, d); d = fmaf(v3.w, k3.w, d);

        d += __shfl_xor_sync(0xffffffffu, d, 16);
        d += __shfl_xor_sync(0xffffffffu, d, 8);
        d += __shfl_xor_sync(0xffffffffu, d, 4);
        d += __shfl_xor_sync(0xffffffffu, d, 2);
        d += __shfl_xor_sync(0xffffffffu, d, 1);

        const float s = d + bkq;
        if (i == lane) myS = s;

        const float mn   = fmaxf(m, s);
        const float corr = fexp2((m - mn) * LOG2E);
        const float w    = fexp2((s - mn) * LOG2E);
        Z = fmaf(Z, corr, w);
        a0.x = fmaf(a0.x, corr, w * v0.x); a0.y = fmaf(a0.y, corr, w * v0.y);
        a0.z = fmaf(a0.z, corr, w * v0.z); a0.w = fmaf(a0.w, corr, w * v0.w);
        a1.x = fmaf(a1.x, corr, w * v1.x); a1.y = fmaf(a1.y, corr, w * v1.y);
        a1.z = fmaf(a1.z, corr, w * v1.z); a1.w = fmaf(a1.w, corr, w * v1.w);
        a2.x = fmaf(a2.x, corr, w * v2.x); a2.y = fmaf(a2.y, corr, w * v2.y);
        a2.z = fmaf(a2.z, corr, w * v2.z); a2.w = fmaf(a2.w, corr, w * v2.w);
        a3.x = fmaf(a3.x, corr, w * v3.x); a3.y = fmaf(a3.y, corr, w * v3.y);
        a3.z = fmaf(a3.z, corr, w * v3.z); a3.w = fmaf(a3.w, corr, w * v3.w);
        m = mn;
    }

    g_raw[b * Tt + t0 + lane] = myS;
    if (lane == 0) { g_pm[pid] = m; g_pz[pid] = Z; }
    float4* pa = (float4*)(g_pacc + (size_t)pid * Hh);
    pa[lane] = a0; pa[32 + lane] = a1; pa[64 + lane] = a2; pa[96 + lane] = a3;
}

// ---------------------------------------------------------------------------
// Kernel 4: combine 64 partials per row, project through Wv, emit outputs.
// All inner loops: batched loads + independent accumulators (MLP fix).
// ---------------------------------------------------------------------------
__global__ __launch_bounds__(256) void k_final(
    const float* __restrict__ Wv, const float* __restrict__ bv,
    float* __restrict__ out)
{
    __shared__ float sm[64], sz[64], ssc[64], sctx[Hh];
    const int b = blockIdx.x, tid = threadIdx.x;

    if (tid < 64) { sm[tid] = g_pm[b * 64 + tid]; sz[tid] = g_pz[b * 64 + tid]; }
    __syncthreads();

    float mstar = -3.0e38f;
#pragma unroll
    for (int i = 0; i < 64; i++) mstar = fmaxf(mstar, sm[i]);
    float Z = 0.f;
#pragma unroll
    for (int i = 0; i < 64; i++) Z += sz[i] * fexp2((sm[i] - mstar) * LOG2E);
    if (tid < 64) ssc[tid] = fexp2((sm[tid] - mstar) * LOG2E);
    __syncthreads();

    const float invZ = 1.f / Z;

    // ctx_enc[e] = (1/Z) * sum_i ssc[i] * pacc[i][e]   (2 e's per thread)
#pragma unroll
    for (int eo = 0; eo < 2; eo++) {
        const int e = tid + eo * 256;
        const float* pb = g_pacc + (size_t)b * 64 * Hh + e;
        float a0 = 0.f, a1 = 0.f, a2 = 0.f, a3 = 0.f;
#pragma unroll
        for (int i = 0; i < 64; i += 8) {
            float v[8];
#pragma unroll
            for (int j = 0; j < 8; j++) v[j] = pb[(size_t)(i + j) * Hh];
#pragma unroll
            for (int j = 0; j < 8; j += 4) {
                a0 = fmaf(v[j + 0], ssc[i + j + 0], a0);
                a1 = fmaf(v[j + 1], ssc[i + j + 1], a1);
                a2 = fmaf(v[j + 2], ssc[i + j + 2], a2);
                a3 = fmaf(v[j + 3], ssc[i + j + 3], a3);
            }
        }
        sctx[e] = ((a0 + a1) + (a2 + a3)) * invZ;
    }
    __syncthreads();

    // context[b,p] = ctx_enc . Wv[:,p] + bv[p]  (batched loads, 4 accs)
    {
        float a0 = 0.f, a1 = 0.f, a2 = 0.f, a3 = 0.f;
#pragma unroll 4
        for (int e0 = 0; e0 < Hh; e0 += 16) {
            float w[16];
#pragma unroll
            for (int j = 0; j < 16; j++) w[j] = Wv[(e0 + j) * Pp + tid];
#pragma unroll
            for (int j = 0; j < 16; j += 4) {
                a0 = fmaf(sctx[e0 + j + 0], w[j + 0], a0);
                a1 = fmaf(sctx[e0 + j + 1], w[j + 1], a1);
                a2 = fmaf(sctx[e0 + j + 2], w[j + 2], a2);
                a3 = fmaf(sctx[e0 + j + 3], w[j + 3], a3);
            }
        }
        out[b * Pp + tid] = ((a0 + a1) + (a2 + a3)) + bv[tid];
    }

    // attn[b,t] = exp(raw - mstar) / Z   (independent iterations)
    float* oat = out + Bb * Pp + b * Tt;
    const float* rr = g_raw + b * Tt;
#pragma unroll
    for (int t0 = 0; t0 < Tt; t0 += 256)
        oat[t0 + tid] = fexp2((rr[t0 + tid] - mstar) * LOG2E) * invZ;
}

// ---------------------------------------------------------------------------
extern "C" void kernel_launch(void* const* d_in, const int* in_sizes, int n_in,
                              void* d_out, int out_size)
{
    const float* dec = (const float*)d_in[0];   // [B, DEC_H]
    const float* enc = (const float*)d_in[1];   // [B, T, ENC_H]
    // d_in[2] = encoder_lens (unused by the reference)
    const float* Wk  = (const float*)d_in[3];   // [ENC_H, P]
    const float* bk  = (const float*)d_in[4];   // [P]
    const float* Wv  = (const float*)d_in[5];   // [ENC_H, P]
    const float* bv  = (const float*)d_in[6];   // [P]
    const float* Wq  = (const float*)d_in[7];   // [DEC_H, P]
    const float* bq  = (const float*)d_in[8];   // [P]
    float* out = (float*)d_out;                 // [B*P] context, then [B*T] attn

    k_query<<<Bb, 256>>>(dec, Wq, bq, bk);
    k_kq<<<dim3(4, Bb), 128>>>(Wk);
    k_stream<<<Bb * CHUNKS, 256>>>(enc);
    k_final<<<Bb, 256>>>(Wv, bv, out);
}